// round 16
// baseline (speedup 1.0000x reference)
#include <cuda_runtime.h>
#include <cuda_fp16.h>
#include <math.h>

#define NN 50000
#define EE 600000
#define CC 128
#define KK 128
#define LDH 136                           // padded smem row, halves (68 half2)

// Scratch (static device globals; no runtime allocation allowed)
__device__ float  g_out[(size_t)NN * CC];      // softplus(h@W0+b0) fp32
__device__ float  g_Pi[(size_t)NN * 256];      // fp32 [pi_f | pi_s] per node
// INTERLEAVED fp16 pj: lane l: halves [8l,8l+4) = f ch 4l..4l+3, [8l+4,8l+8) = q.
__device__ __half g_Pj16[(size_t)NN * 256];
__device__ float  g_aggr[(size_t)NN * CC];     // segment-sum result
__device__ float  g_stats[2 * CC];             // per-channel sum, sumsq
__device__ __half g_W016T[128 * 128];          // W0 transposed [n][k], fp16
__device__ __half g_Wcat16T[512 * 128];        // packed weights, TRANSPOSED [n][k], fp16
// CSR scratch (g_deg self-cleans in assign_off)
__device__ int    g_deg[NN];
__device__ int    g_roff[NN];
__device__ int    g_cursor[NN];
__device__ int    g_total;
__device__ int    g_ticket;                    // work-steal counter for edge_msg
__device__ int2   g_epack[EE];                 // (src, e-bits) grouped by dst row

__device__ __forceinline__ float sp_f(float x) {
    return x > 15.0f ? x : __logf(1.0f + __expf(x));
}
__device__ __forceinline__ float sigm_f(float x) {
    float t;
    asm("tanh.approx.f32 %0, %1;" : "=f"(t) : "f"(x * 0.5f));
    return fmaf(0.5f, t, 0.5f);
}

// ---------------- weight packing: W0T + WcatT (fp16, [n][k]) + zero stats ----
__global__ void prep_pack(const float* __restrict__ W0,
                          const float* __restrict__ Wf, const float* __restrict__ Ws) {
    int idx = blockIdx.x * blockDim.x + threadIdx.x;   // n_all*128 + k, n_all 0..639
    if (idx < 640 * 128) {
        int n_all = idx >> 7;
        int k = idx & 127;
        float v;
        if (n_all < 128) {
            v = W0[k * 128 + n_all];
            g_W016T[idx] = __float2half(v);
        } else {
            int n = n_all - 128;
            if (n < 128)      v = Wf[k * 128 + n];
            else if (n < 256) v = Ws[k * 128 + (n - 128)];
            else if (n < 384) v = Wf[(128 + k) * 128 + (n - 256)];
            else              v = Ws[(128 + k) * 128 + (n - 384)];
            g_Wcat16T[(size_t)n * 128 + k] = __float2half(v);
        }
    }
    if (blockIdx.x == 0) {
        if (threadIdx.x < 2 * CC) g_stats[threadIdx.x] = 0.0f;
        if (threadIdx.x == 0) g_ticket = 0;
    }
}

// ---------------- Fused node GEMMs (fp16 tensor core) ----------------------
__global__ void __launch_bounds__(256, 2)
node_gemms(const float* __restrict__ h, const float* __restrict__ bias) {
    extern __shared__ __half smemh[];
    __half* As = smemh;                 // [128][LDH]  (h16, then out16)
    __half* Bs = smemh + 128 * LDH;     // [128][LDH]  (weight tiles [n][k])
    int tid = threadIdx.x;
    int row0 = blockIdx.x * 128;

#pragma unroll
    for (int l = 0; l < 16; l++) {
        int f = tid + l * 256;
        int r = f >> 5;
        int c4 = (f & 31) << 2;
        int gr = row0 + r;
        float4 v = make_float4(0.f, 0.f, 0.f, 0.f);
        if (gr < NN) v = *(const float4*)(h + (size_t)gr * KK + c4);
        __half2 h0 = __floats2half2_rn(v.x, v.y);
        __half2 h1 = __floats2half2_rn(v.z, v.w);
        uint2 u;
        u.x = *(unsigned*)&h0;
        u.y = *(unsigned*)&h1;
        *(uint2*)(As + r * LDH + c4) = u;
    }
#pragma unroll
    for (int l = 0; l < 8; l++) {
        int idx = tid + l * 256;
        int r = idx >> 4;
        int c8 = (idx & 15) << 3;
        *(int4*)(Bs + r * LDH + c8) = *(const int4*)(g_W016T + (size_t)r * CC + c8);
    }
    __syncthreads();

    int lane = tid & 31;
    int w = tid >> 5;
    int g = lane >> 2, tig = lane & 3;
    int wm = (w & 1) * 64, wn = (w >> 1) * 32;

    const unsigned* As2 = (const unsigned*)As;
    const unsigned* Bs2 = (const unsigned*)Bs;

    float acc[4][4][4];

#pragma unroll
    for (int mt = 0; mt < 4; mt++)
#pragma unroll
        for (int nt = 0; nt < 4; nt++)
#pragma unroll
            for (int q = 0; q < 4; q++) acc[mt][nt][q] = 0.f;

#pragma unroll
    for (int ks = 0; ks < 8; ks++) {
        int kk = ks * 8;
        unsigned a[4][4], b[4][2];
#pragma unroll
        for (int mt = 0; mt < 4; mt++) {
            int r = wm + mt * 16 + g;
            a[mt][0] = As2[r * 68 + kk + tig];
            a[mt][1] = As2[(r + 8) * 68 + kk + tig];
            a[mt][2] = As2[r * 68 + kk + 4 + tig];
            a[mt][3] = As2[(r + 8) * 68 + kk + 4 + tig];
        }
#pragma unroll
        for (int nt = 0; nt < 4; nt++) {
            int r = wn + nt * 8 + g;
            b[nt][0] = Bs2[r * 68 + kk + tig];
            b[nt][1] = Bs2[r * 68 + kk + 4 + tig];
        }
#pragma unroll
        for (int mt = 0; mt < 4; mt++)
#pragma unroll
            for (int nt = 0; nt < 4; nt++) {
                asm volatile(
                    "mma.sync.aligned.m16n8k16.row.col.f32.f16.f16.f32 "
                    "{%0,%1,%2,%3}, {%4,%5,%6,%7}, {%8,%9}, {%0,%1,%2,%3};"
                    : "+f"(acc[mt][nt][0]), "+f"(acc[mt][nt][1]),
                      "+f"(acc[mt][nt][2]), "+f"(acc[mt][nt][3])
                    : "r"(a[mt][0]), "r"(a[mt][1]), "r"(a[mt][2]), "r"(a[mt][3]),
                      "r"(b[nt][0]), "r"(b[nt][1]));
            }
    }
    __syncthreads();

    // Stage-1 epilogue
#pragma unroll
    for (int mt = 0; mt < 4; mt++) {
#pragma unroll
        for (int nt = 0; nt < 4; nt++) {
            int r0 = wm + mt * 16 + g;
            int r1 = r0 + 8;
            int col = wn + nt * 8 + tig * 2;
            float bb0 = bias[col], bb1 = bias[col + 1];
            float o0 = sp_f(acc[mt][nt][0] + bb0);
            float o1 = sp_f(acc[mt][nt][1] + bb1);
            float o2 = sp_f(acc[mt][nt][2] + bb0);
            float o3 = sp_f(acc[mt][nt][3] + bb1);
            __half2 h01 = __floats2half2_rn(o0, o1);
            __half2 h23 = __floats2half2_rn(o2, o3);
            *(unsigned*)(As + r0 * LDH + col) = *(unsigned*)&h01;
            *(unsigned*)(As + r1 * LDH + col) = *(unsigned*)&h23;
            int gr0 = row0 + r0, gr1 = row0 + r1;
            if (gr0 < NN) *(float2*)(g_out + (size_t)gr0 * CC + col) = make_float2(o0, o1);
            if (gr1 < NN) *(float2*)(g_out + (size_t)gr1 * CC + col) = make_float2(o2, o3);
        }
    }
    __syncthreads();

    // ---- Stage 2: out @ Wcat, 4 n-blocks ----
    for (int nblk = 0; nblk < 4; nblk++) {
#pragma unroll
        for (int l = 0; l < 8; l++) {
            int idx = tid + l * 256;
            int r = idx >> 4;
            int c8 = (idx & 15) << 3;
            *(int4*)(Bs + r * LDH + c8) =
                *(const int4*)(g_Wcat16T + ((size_t)(nblk * 128 + r)) * CC + c8);
        }
        __syncthreads();

#pragma unroll
        for (int mt = 0; mt < 4; mt++)
#pragma unroll
            for (int nt = 0; nt < 4; nt++)
#pragma unroll
                for (int q = 0; q < 4; q++) acc[mt][nt][q] = 0.f;

#pragma unroll
        for (int ks = 0; ks < 8; ks++) {
            int kk = ks * 8;
            unsigned a[4][4], b[4][2];
#pragma unroll
            for (int mt = 0; mt < 4; mt++) {
                int r = wm + mt * 16 + g;
                a[mt][0] = As2[r * 68 + kk + tig];
                a[mt][1] = As2[(r + 8) * 68 + kk + tig];
                a[mt][2] = As2[r * 68 + kk + 4 + tig];
                a[mt][3] = As2[(r + 8) * 68 + kk + 4 + tig];
            }
#pragma unroll
            for (int nt = 0; nt < 4; nt++) {
                int r = wn + nt * 8 + g;
                b[nt][0] = Bs2[r * 68 + kk + tig];
                b[nt][1] = Bs2[r * 68 + kk + 4 + tig];
            }
#pragma unroll
            for (int mt = 0; mt < 4; mt++)
#pragma unroll
                for (int nt = 0; nt < 4; nt++) {
                    asm volatile(
                        "mma.sync.aligned.m16n8k16.row.col.f32.f16.f16.f32 "
                        "{%0,%1,%2,%3}, {%4,%5,%6,%7}, {%8,%9}, {%0,%1,%2,%3};"
                        : "+f"(acc[mt][nt][0]), "+f"(acc[mt][nt][1]),
                          "+f"(acc[mt][nt][2]), "+f"(acc[mt][nt][3])
                        : "r"(a[mt][0]), "r"(a[mt][1]), "r"(a[mt][2]), "r"(a[mt][3]),
                          "r"(b[nt][0]), "r"(b[nt][1]));
                }
        }

#pragma unroll
        for (int mt = 0; mt < 4; mt++) {
#pragma unroll
            for (int nt = 0; nt < 4; nt++) {
                int gr0 = row0 + wm + mt * 16 + g;
                int gr1 = gr0 + 8;
                float d0 = acc[mt][nt][0], d1 = acc[mt][nt][1];
                float d2 = acc[mt][nt][2], d3 = acc[mt][nt][3];
                if (nblk < 2) {
                    int col = nblk * 128 + wn + nt * 8 + tig * 2;
                    if (gr0 < NN) *(float2*)(g_Pi + (size_t)gr0 * 256 + col) = make_float2(d0, d1);
                    if (gr1 < NN) *(float2*)(g_Pi + (size_t)gr1 * 256 + col) = make_float2(d2, d3);
                } else {
                    int c0 = wn + nt * 8 + tig * 2;
                    int hoff = ((c0 >> 2) << 3) + (c0 & 3) + (nblk == 3 ? 4 : 0);
                    __half2 h01 = __floats2half2_rn(d0, d1);
                    __half2 h23 = __floats2half2_rn(d2, d3);
                    if (gr0 < NN) *(unsigned*)(g_Pj16 + (size_t)gr0 * 256 + hoff) = *(unsigned*)&h01;
                    if (gr1 < NN) *(unsigned*)(g_Pj16 + (size_t)gr1 * 256 + hoff) = *(unsigned*)&h23;
                }
            }
        }
        __syncthreads();
    }
}

// ---------------- CSR build ----------------
__global__ void hist(const int* __restrict__ ei) {
    int e = blockIdx.x * blockDim.x + threadIdx.x;
    if (e == 0) g_total = 0;
    if (e < EE) atomicAdd(&g_deg[ei[EE + e]], 1);
}

__global__ void assign_off() {
    int i = blockIdx.x * blockDim.x + threadIdx.x;
    if (i < NN) {
        int d = g_deg[i];
        g_deg[i] = 0;                    // self-clean (replaces host memset)
        int r = atomicAdd(&g_total, d);
        g_roff[i] = r;
        g_cursor[i] = r;
    }
}

// ---------------- e = softplus(edge_attr @ Wsh + bsh) fused with CSR scatter
__global__ void edge_gauss_scatter(const float* __restrict__ ea,
                                   const float* __restrict__ Wsh,
                                   const float* __restrict__ bsh,
                                   const int* __restrict__ ei) {
    int t = blockIdx.x * blockDim.x + threadIdx.x;
    int e = t >> 3;
    if (e >= EE) return;
    int l = t & 7;
    const float4* base = (const float4*)(ea + (size_t)e * 128) + l * 4;
    const float4* wb = (const float4*)Wsh + l * 4;
    float4 a0 = base[0], a1 = base[1], a2 = base[2], a3 = base[3];
    float4 w0 = wb[0], w1 = wb[1], w2 = wb[2], w3 = wb[3];
    float d = a0.x * w0.x + a0.y * w0.y + a0.z * w0.z + a0.w * w0.w
            + a1.x * w1.x + a1.y * w1.y + a1.z * w1.z + a1.w * w1.w
            + a2.x * w2.x + a2.y * w2.y + a2.z * w2.z + a2.w * w2.w
            + a3.x * w3.x + a3.y * w3.y + a3.z * w3.z + a3.w * w3.w;
#pragma unroll
    for (int o = 4; o; o >>= 1) d += __shfl_xor_sync(0xFFFFFFFFu, d, o);
    if (l == 0) {
        float ev = sp_f(d + bsh[0]);
        int src = __ldg(ei + e);
        int dst = __ldg(ei + EE + e);
        int pos = atomicAdd(&g_cursor[dst], 1);
        g_epack[pos] = make_int2(src, __float_as_int(ev));
    }
}

// ---------------- CSR edge messages + fused BN stats --------------------
// Software-pipelined: double-buffered 4-edge groups; raw uint4 gathers are
// in flight for group g+1 while group g's math executes. Remainders via
// clamped indices + validity-mask multiplies.
__device__ __forceinline__ void fetch_group(int kk, int end, int lane,
                                            int2* p, uint4* u) {
#pragma unroll
    for (int j = 0; j < 4; j++) {
        int idx = kk + j;
        if (idx > end - 1) idx = end - 1;
        int2 pp = g_epack[idx];
        p[j] = pp;
        u[j] = *(const uint4*)(g_Pj16 + (size_t)pp.x * 256 + lane * 8);
    }
}

__device__ __forceinline__ void compute_group(float4& acc, const float4& pif, const float4& pis,
                                              const int2* p, const uint4* u, int kk, int end,
                                              const float4& wfe, const float4& wse) {
#pragma unroll
    for (int j = 0; j < 4; j++) {
        float m = (kk + j < end) ? 1.0f : 0.0f;
        float ev = __int_as_float(p[j].y);
        float2 f01 = __half22float2(*(__half2*)&u[j].x);
        float2 f23 = __half22float2(*(__half2*)&u[j].y);
        float2 q01 = __half22float2(*(__half2*)&u[j].z);
        float2 q23 = __half22float2(*(__half2*)&u[j].w);
        acc.x += m * sigm_f(pif.x + f01.x + ev * wfe.x) * sp_f(pis.x + q01.x + ev * wse.x);
        acc.y += m * sigm_f(pif.y + f01.y + ev * wfe.y) * sp_f(pis.y + q01.y + ev * wse.y);
        acc.z += m * sigm_f(pif.z + f23.x + ev * wfe.z) * sp_f(pis.z + q23.x + ev * wse.z);
        acc.w += m * sigm_f(pif.w + f23.y + ev * wfe.w) * sp_f(pis.w + q23.y + ev * wse.w);
    }
}

__global__ void __launch_bounds__(256)
edge_msg_csr(const float* __restrict__ Wf, const float* __restrict__ Ws,
             const float* __restrict__ bf, const float* __restrict__ bs) {
    __shared__ float s_stats[2 * CC];
    int tid = threadIdx.x;
    int lane = tid & 31;
    int c = lane * 4;
    s_stats[tid] = 0.0f;
    __syncthreads();

    float4 wfe = *(const float4*)(Wf + 256 * 128 + c);
    float4 wse = *(const float4*)(Ws + 256 * 128 + c);
    float4 bfv = *(const float4*)(bf + c);
    float4 bsv = *(const float4*)(bs + c);

    float lsum[4] = {}, lsq[4] = {};

    int i = 0;
    if (lane == 0) i = atomicAdd(&g_ticket, 1);
    i = __shfl_sync(0xFFFFFFFFu, i, 0);

    while (i < NN) {
        int nexti = 0;
        if (lane == 0) nexti = atomicAdd(&g_ticket, 1);   // prefetch next ticket

        const float4* Pi = (const float4*)(g_Pi + (size_t)i * 256);
        float4 pif = Pi[lane];
        float4 pis = Pi[32 + lane];
        pif.x += bfv.x; pif.y += bfv.y; pif.z += bfv.z; pif.w += bfv.w;
        pis.x += bsv.x; pis.y += bsv.y; pis.z += bsv.z; pis.w += bsv.w;
        int k = g_roff[i];
        int end = g_cursor[i];
        float4 acc = make_float4(0.f, 0.f, 0.f, 0.f);

        if (k < end) {
            int2 pA[4]; uint4 uA[4];
            int2 pB[4]; uint4 uB[4];
            fetch_group(k, end, lane, pA, uA);
            int kk = k;
            while (true) {
                int kn = kk + 4;
                if (kn < end) fetch_group(kn, end, lane, pB, uB);   // overlap with A math
                compute_group(acc, pif, pis, pA, uA, kk, end, wfe, wse);
                kk = kn;
                if (kk >= end) break;
                kn = kk + 4;
                if (kn < end) fetch_group(kn, end, lane, pA, uA);   // overlap with B math
                compute_group(acc, pif, pis, pB, uB, kk, end, wfe, wse);
                kk = kn;
                if (kk >= end) break;
            }
        }

        *(float4*)(g_aggr + (size_t)i * CC + c) = acc;
        lsum[0] += acc.x; lsum[1] += acc.y; lsum[2] += acc.z; lsum[3] += acc.w;
        lsq[0] += acc.x * acc.x; lsq[1] += acc.y * acc.y; lsq[2] += acc.z * acc.z; lsq[3] += acc.w * acc.w;

        i = __shfl_sync(0xFFFFFFFFu, nexti, 0);
    }

#pragma unroll
    for (int j = 0; j < 4; j++) {
        atomicAdd(&s_stats[c + j], lsum[j]);
        atomicAdd(&s_stats[CC + c + j], lsq[j]);
    }
    __syncthreads();
    if (tid < 64) {
        float4 v = *(float4*)&s_stats[tid * 4];
        float* dstp = g_stats + tid * 4;
        asm volatile("red.global.add.v4.f32 [%0], {%1, %2, %3, %4};"
                     :: "l"(dstp), "f"(v.x), "f"(v.y), "f"(v.z), "f"(v.w)
                     : "memory");
    }
}

// ---------------- out_final = 2*out + batchnorm(aggr) ----------------
__global__ void finalize(const float* __restrict__ gamma, const float* __restrict__ beta,
                         float* __restrict__ out) {
    int i4 = blockIdx.x * blockDim.x + threadIdx.x;
    if (i4 >= NN * 32) return;
    int c = (i4 & 31) * 4;
    float4 a = *(const float4*)(g_aggr + (size_t)i4 * 4);
    float4 o = *(const float4*)(g_out + (size_t)i4 * 4);
    const float inv = 1.0f / NN;
    float4 r;
#pragma unroll
    for (int j = 0; j < 4; j++) {
        float sum = g_stats[c + j];
        float sq = g_stats[CC + c + j];
        float mean = sum * inv;
        float var = sq * inv - mean * mean;
        float scale = rsqrtf(var + 1e-5f) * gamma[c + j];
        float av = (&a.x)[j];
        float ov = (&o.x)[j];
        (&r.x)[j] = 2.0f * ov + (av - mean) * scale + beta[c + j];
    }
    *(float4*)(out + (size_t)i4 * 4) = r;
}

extern "C" void kernel_launch(void* const* d_in, const int* in_sizes, int n_in,
                              void* d_out, int out_size) {
    const float* h    = (const float*)d_in[0];
    const int*   ei   = (const int*)d_in[1];
    const float* ea   = (const float*)d_in[3];
    const float* W0   = (const float*)d_in[4];
    const float* b0   = (const float*)d_in[5];
    const float* Wsh  = (const float*)d_in[6];
    const float* bsh  = (const float*)d_in[7];
    const float* Wf   = (const float*)d_in[8];
    const float* bf   = (const float*)d_in[9];
    const float* Ws   = (const float*)d_in[10];
    const float* bs   = (const float*)d_in[11];
    const float* gamma = (const float*)d_in[12];
    const float* beta  = (const float*)d_in[13];
    float* out = (float*)d_out;

    static cudaStream_t s2 = nullptr, s3 = nullptr;
    static cudaEvent_t evFork = nullptr, evJoin2 = nullptr, evJoin3 = nullptr;
    static bool attrSet = false;
    const int SMEM_NG = 2 * 128 * LDH * (int)sizeof(__half);
    if (!s2) {
        cudaStreamCreateWithFlags(&s2, cudaStreamNonBlocking);
        cudaStreamCreateWithFlags(&s3, cudaStreamNonBlocking);
        cudaEventCreateWithFlags(&evFork, cudaEventDisableTiming);
        cudaEventCreateWithFlags(&evJoin2, cudaEventDisableTiming);
        cudaEventCreateWithFlags(&evJoin3, cudaEventDisableTiming);
    }
    if (!attrSet) {
        cudaFuncSetAttribute(node_gemms, cudaFuncAttributeMaxDynamicSharedMemorySize, SMEM_NG);
        attrSet = true;
    }

    // ---- fork ----
    cudaEventRecord(evFork, 0);
    cudaStreamWaitEvent(s2, evFork, 0);
    cudaStreamWaitEvent(s3, evFork, 0);

    // branch A (s2): CSR build + edge gaussian
    hist<<<(EE + 255) / 256, 256, 0, s2>>>(ei);
    assign_off<<<(NN + 255) / 256, 256, 0, s2>>>();
    edge_gauss_scatter<<<(EE * 8 + 255) / 256, 256, 0, s2>>>(ea, Wsh, bsh, ei);
    cudaEventRecord(evJoin2, s2);

    // branch B (s3): weight pack + fused node GEMMs (tensor core)
    prep_pack<<<(640 * 128 + 255) / 256, 256, 0, s3>>>(W0, Wf, Ws);
    node_gemms<<<(NN + 127) / 128, 256, SMEM_NG, s3>>>(h, b0);
    cudaEventRecord(evJoin3, s3);

    // ---- join ----
    cudaStreamWaitEvent(0, evJoin2, 0);
    cudaStreamWaitEvent(0, evJoin3, 0);

    edge_msg_csr<<<1024, 256>>>(Wf, Ws, bf, bs);
    finalize<<<(NN * 32 + 255) / 256, 256>>>(gamma, beta, out);
}

// round 17
// speedup vs baseline: 1.0543x; 1.0543x over previous
#include <cuda_runtime.h>
#include <cuda_fp16.h>
#include <math.h>

#define NN 50000
#define EE 600000
#define CC 128
#define KK 128
#define LDH 136                           // padded smem row, halves (68 half2)

// Scratch (static device globals; no runtime allocation allowed)
__device__ float  g_out[(size_t)NN * CC];      // softplus(h@W0+b0) fp32
__device__ float  g_Pi[(size_t)NN * 256];      // fp32 [pi_f | pi_s] per node
// INTERLEAVED fp16 pj: lane l: halves [8l,8l+4) = f ch 4l..4l+3, [8l+4,8l+8) = q.
__device__ __half g_Pj16[(size_t)NN * 256];
__device__ float  g_aggr[(size_t)NN * CC];     // segment-sum result
__device__ float  g_stats[2 * CC];             // per-channel sum, sumsq
__device__ __half g_W016T[128 * 128];          // W0 transposed [n][k], fp16
__device__ __half g_Wcat16T[512 * 128];        // packed weights, TRANSPOSED [n][k], fp16
// CSR scratch (g_deg self-cleans in assign_off)
__device__ int    g_deg[NN];
__device__ int    g_roff[NN];
__device__ int    g_cursor[NN];
__device__ int    g_total;
__device__ int    g_ticket;                    // work-steal counter for edge_msg
__device__ int2   g_epack[EE];                 // (src, e-bits) grouped by dst row

__device__ __forceinline__ float sp_f(float x) {
    return x > 15.0f ? x : __logf(1.0f + __expf(x));
}
__device__ __forceinline__ float sigm_f(float x) {
    float t;
    asm("tanh.approx.f32 %0, %1;" : "=f"(t) : "f"(x * 0.5f));
    return fmaf(0.5f, t, 0.5f);
}

// ---------------- weight packing: W0T + WcatT (fp16, [n][k]) + zero stats ----
__global__ void prep_pack(const float* __restrict__ W0,
                          const float* __restrict__ Wf, const float* __restrict__ Ws) {
    int idx = blockIdx.x * blockDim.x + threadIdx.x;   // n_all*128 + k, n_all 0..639
    if (idx < 640 * 128) {
        int n_all = idx >> 7;
        int k = idx & 127;
        float v;
        if (n_all < 128) {
            v = W0[k * 128 + n_all];
            g_W016T[idx] = __float2half(v);
        } else {
            int n = n_all - 128;
            if (n < 128)      v = Wf[k * 128 + n];
            else if (n < 256) v = Ws[k * 128 + (n - 128)];
            else if (n < 384) v = Wf[(128 + k) * 128 + (n - 256)];
            else              v = Ws[(128 + k) * 128 + (n - 384)];
            g_Wcat16T[(size_t)n * 128 + k] = __float2half(v);
        }
    }
    if (blockIdx.x == 0) {
        if (threadIdx.x < 2 * CC) g_stats[threadIdx.x] = 0.0f;
        if (threadIdx.x == 0) g_ticket = 0;
    }
}

// ---------------- Fused node GEMMs (fp16 tensor core) ----------------------
__global__ void __launch_bounds__(256, 2)
node_gemms(const float* __restrict__ h, const float* __restrict__ bias) {
    extern __shared__ __half smemh[];
    __half* As = smemh;                 // [128][LDH]  (h16, then out16)
    __half* Bs = smemh + 128 * LDH;     // [128][LDH]  (weight tiles [n][k])
    int tid = threadIdx.x;
    int row0 = blockIdx.x * 128;

#pragma unroll
    for (int l = 0; l < 16; l++) {
        int f = tid + l * 256;
        int r = f >> 5;
        int c4 = (f & 31) << 2;
        int gr = row0 + r;
        float4 v = make_float4(0.f, 0.f, 0.f, 0.f);
        if (gr < NN) v = *(const float4*)(h + (size_t)gr * KK + c4);
        __half2 h0 = __floats2half2_rn(v.x, v.y);
        __half2 h1 = __floats2half2_rn(v.z, v.w);
        uint2 u;
        u.x = *(unsigned*)&h0;
        u.y = *(unsigned*)&h1;
        *(uint2*)(As + r * LDH + c4) = u;
    }
#pragma unroll
    for (int l = 0; l < 8; l++) {
        int idx = tid + l * 256;
        int r = idx >> 4;
        int c8 = (idx & 15) << 3;
        *(int4*)(Bs + r * LDH + c8) = *(const int4*)(g_W016T + (size_t)r * CC + c8);
    }
    __syncthreads();

    int lane = tid & 31;
    int w = tid >> 5;
    int g = lane >> 2, tig = lane & 3;
    int wm = (w & 1) * 64, wn = (w >> 1) * 32;

    const unsigned* As2 = (const unsigned*)As;
    const unsigned* Bs2 = (const unsigned*)Bs;

    float acc[4][4][4];

#pragma unroll
    for (int mt = 0; mt < 4; mt++)
#pragma unroll
        for (int nt = 0; nt < 4; nt++)
#pragma unroll
            for (int q = 0; q < 4; q++) acc[mt][nt][q] = 0.f;

#pragma unroll
    for (int ks = 0; ks < 8; ks++) {
        int kk = ks * 8;
        unsigned a[4][4], b[4][2];
#pragma unroll
        for (int mt = 0; mt < 4; mt++) {
            int r = wm + mt * 16 + g;
            a[mt][0] = As2[r * 68 + kk + tig];
            a[mt][1] = As2[(r + 8) * 68 + kk + tig];
            a[mt][2] = As2[r * 68 + kk + 4 + tig];
            a[mt][3] = As2[(r + 8) * 68 + kk + 4 + tig];
        }
#pragma unroll
        for (int nt = 0; nt < 4; nt++) {
            int r = wn + nt * 8 + g;
            b[nt][0] = Bs2[r * 68 + kk + tig];
            b[nt][1] = Bs2[r * 68 + kk + 4 + tig];
        }
#pragma unroll
        for (int mt = 0; mt < 4; mt++)
#pragma unroll
            for (int nt = 0; nt < 4; nt++) {
                asm volatile(
                    "mma.sync.aligned.m16n8k16.row.col.f32.f16.f16.f32 "
                    "{%0,%1,%2,%3}, {%4,%5,%6,%7}, {%8,%9}, {%0,%1,%2,%3};"
                    : "+f"(acc[mt][nt][0]), "+f"(acc[mt][nt][1]),
                      "+f"(acc[mt][nt][2]), "+f"(acc[mt][nt][3])
                    : "r"(a[mt][0]), "r"(a[mt][1]), "r"(a[mt][2]), "r"(a[mt][3]),
                      "r"(b[nt][0]), "r"(b[nt][1]));
            }
    }
    __syncthreads();

    // Stage-1 epilogue
#pragma unroll
    for (int mt = 0; mt < 4; mt++) {
#pragma unroll
        for (int nt = 0; nt < 4; nt++) {
            int r0 = wm + mt * 16 + g;
            int r1 = r0 + 8;
            int col = wn + nt * 8 + tig * 2;
            float bb0 = bias[col], bb1 = bias[col + 1];
            float o0 = sp_f(acc[mt][nt][0] + bb0);
            float o1 = sp_f(acc[mt][nt][1] + bb1);
            float o2 = sp_f(acc[mt][nt][2] + bb0);
            float o3 = sp_f(acc[mt][nt][3] + bb1);
            __half2 h01 = __floats2half2_rn(o0, o1);
            __half2 h23 = __floats2half2_rn(o2, o3);
            *(unsigned*)(As + r0 * LDH + col) = *(unsigned*)&h01;
            *(unsigned*)(As + r1 * LDH + col) = *(unsigned*)&h23;
            int gr0 = row0 + r0, gr1 = row0 + r1;
            if (gr0 < NN) *(float2*)(g_out + (size_t)gr0 * CC + col) = make_float2(o0, o1);
            if (gr1 < NN) *(float2*)(g_out + (size_t)gr1 * CC + col) = make_float2(o2, o3);
        }
    }
    __syncthreads();

    // ---- Stage 2: out @ Wcat, 4 n-blocks ----
    for (int nblk = 0; nblk < 4; nblk++) {
#pragma unroll
        for (int l = 0; l < 8; l++) {
            int idx = tid + l * 256;
            int r = idx >> 4;
            int c8 = (idx & 15) << 3;
            *(int4*)(Bs + r * LDH + c8) =
                *(const int4*)(g_Wcat16T + ((size_t)(nblk * 128 + r)) * CC + c8);
        }
        __syncthreads();

#pragma unroll
        for (int mt = 0; mt < 4; mt++)
#pragma unroll
            for (int nt = 0; nt < 4; nt++)
#pragma unroll
                for (int q = 0; q < 4; q++) acc[mt][nt][q] = 0.f;

#pragma unroll
        for (int ks = 0; ks < 8; ks++) {
            int kk = ks * 8;
            unsigned a[4][4], b[4][2];
#pragma unroll
            for (int mt = 0; mt < 4; mt++) {
                int r = wm + mt * 16 + g;
                a[mt][0] = As2[r * 68 + kk + tig];
                a[mt][1] = As2[(r + 8) * 68 + kk + tig];
                a[mt][2] = As2[r * 68 + kk + 4 + tig];
                a[mt][3] = As2[(r + 8) * 68 + kk + 4 + tig];
            }
#pragma unroll
            for (int nt = 0; nt < 4; nt++) {
                int r = wn + nt * 8 + g;
                b[nt][0] = Bs2[r * 68 + kk + tig];
                b[nt][1] = Bs2[r * 68 + kk + 4 + tig];
            }
#pragma unroll
            for (int mt = 0; mt < 4; mt++)
#pragma unroll
                for (int nt = 0; nt < 4; nt++) {
                    asm volatile(
                        "mma.sync.aligned.m16n8k16.row.col.f32.f16.f16.f32 "
                        "{%0,%1,%2,%3}, {%4,%5,%6,%7}, {%8,%9}, {%0,%1,%2,%3};"
                        : "+f"(acc[mt][nt][0]), "+f"(acc[mt][nt][1]),
                          "+f"(acc[mt][nt][2]), "+f"(acc[mt][nt][3])
                        : "r"(a[mt][0]), "r"(a[mt][1]), "r"(a[mt][2]), "r"(a[mt][3]),
                          "r"(b[nt][0]), "r"(b[nt][1]));
                }
        }

#pragma unroll
        for (int mt = 0; mt < 4; mt++) {
#pragma unroll
            for (int nt = 0; nt < 4; nt++) {
                int gr0 = row0 + wm + mt * 16 + g;
                int gr1 = gr0 + 8;
                float d0 = acc[mt][nt][0], d1 = acc[mt][nt][1];
                float d2 = acc[mt][nt][2], d3 = acc[mt][nt][3];
                if (nblk < 2) {
                    int col = nblk * 128 + wn + nt * 8 + tig * 2;
                    if (gr0 < NN) *(float2*)(g_Pi + (size_t)gr0 * 256 + col) = make_float2(d0, d1);
                    if (gr1 < NN) *(float2*)(g_Pi + (size_t)gr1 * 256 + col) = make_float2(d2, d3);
                } else {
                    int c0 = wn + nt * 8 + tig * 2;
                    int hoff = ((c0 >> 2) << 3) + (c0 & 3) + (nblk == 3 ? 4 : 0);
                    __half2 h01 = __floats2half2_rn(d0, d1);
                    __half2 h23 = __floats2half2_rn(d2, d3);
                    if (gr0 < NN) *(unsigned*)(g_Pj16 + (size_t)gr0 * 256 + hoff) = *(unsigned*)&h01;
                    if (gr1 < NN) *(unsigned*)(g_Pj16 + (size_t)gr1 * 256 + hoff) = *(unsigned*)&h23;
                }
            }
        }
        __syncthreads();
    }
}

// ---------------- CSR build ----------------
__global__ void hist(const int* __restrict__ ei) {
    int e = blockIdx.x * blockDim.x + threadIdx.x;
    if (e == 0) g_total = 0;
    if (e < EE) atomicAdd(&g_deg[ei[EE + e]], 1);
}

__global__ void assign_off() {
    int i = blockIdx.x * blockDim.x + threadIdx.x;
    if (i < NN) {
        int d = g_deg[i];
        g_deg[i] = 0;                    // self-clean (replaces host memset)
        int r = atomicAdd(&g_total, d);
        g_roff[i] = r;
        g_cursor[i] = r;
    }
}

// ---------------- e = softplus(edge_attr @ Wsh + bsh) fused with CSR scatter
// 4 lanes per edge; each lane reads 128B contiguous (8 x float4, MLP=8);
// warp = 4KB perfectly coalesced; 2-shfl reduce.
__global__ void edge_gauss_scatter(const float* __restrict__ ea,
                                   const float* __restrict__ Wsh,
                                   const float* __restrict__ bsh,
                                   const int* __restrict__ ei) {
    int t = blockIdx.x * blockDim.x + threadIdx.x;
    int e = t >> 2;
    if (e >= EE) return;
    int l = t & 3;
    const float4* base = (const float4*)(ea + (size_t)e * 128) + l * 8;
    const float4* wb = (const float4*)Wsh + l * 8;
    float d = 0.0f;
#pragma unroll
    for (int j = 0; j < 8; j++) {
        float4 a = base[j];
        float4 w = wb[j];
        d += a.x * w.x + a.y * w.y + a.z * w.z + a.w * w.w;
    }
    d += __shfl_xor_sync(0xFFFFFFFFu, d, 2);
    d += __shfl_xor_sync(0xFFFFFFFFu, d, 1);
    if (l == 0) {
        float ev = sp_f(d + bsh[0]);
        int src = __ldg(ei + e);
        int dst = __ldg(ei + EE + e);
        int pos = atomicAdd(&g_cursor[dst], 1);
        g_epack[pos] = make_int2(src, __float_as_int(ev));
    }
}

// ---------------- CSR edge messages + fused BN stats (work-stealing) ------
__device__ __forceinline__ void pj_load(int src, int lane, float4& f, float4& q) {
    uint4 v = *(const uint4*)(g_Pj16 + (size_t)src * 256 + lane * 8);
    float2 f01 = __half22float2(*(__half2*)&v.x);
    float2 f23 = __half22float2(*(__half2*)&v.y);
    float2 q01 = __half22float2(*(__half2*)&v.z);
    float2 q23 = __half22float2(*(__half2*)&v.w);
    f = make_float4(f01.x, f01.y, f23.x, f23.y);
    q = make_float4(q01.x, q01.y, q23.x, q23.y);
}

__device__ __forceinline__ void msg_add(float4& acc, const float4& pif, const float4& pis,
                                        const float4& f, const float4& q, float ev,
                                        const float4& wfe, const float4& wse) {
    acc.x += sigm_f(pif.x + f.x + ev * wfe.x) * sp_f(pis.x + q.x + ev * wse.x);
    acc.y += sigm_f(pif.y + f.y + ev * wfe.y) * sp_f(pis.y + q.y + ev * wse.y);
    acc.z += sigm_f(pif.z + f.z + ev * wfe.z) * sp_f(pis.z + q.z + ev * wse.z);
    acc.w += sigm_f(pif.w + f.w + ev * wfe.w) * sp_f(pis.w + q.w + ev * wse.w);
}

__global__ void __launch_bounds__(256, 3)
edge_msg_csr(const float* __restrict__ Wf, const float* __restrict__ Ws,
             const float* __restrict__ bf, const float* __restrict__ bs) {
    __shared__ float s_stats[2 * CC];
    int tid = threadIdx.x;
    int lane = tid & 31;
    int c = lane * 4;
    s_stats[tid] = 0.0f;
    __syncthreads();

    float4 wfe = *(const float4*)(Wf + 256 * 128 + c);
    float4 wse = *(const float4*)(Ws + 256 * 128 + c);
    float4 bfv = *(const float4*)(bf + c);
    float4 bsv = *(const float4*)(bs + c);

    float lsum[4] = {}, lsq[4] = {};

    int i = 0;
    if (lane == 0) i = atomicAdd(&g_ticket, 1);
    i = __shfl_sync(0xFFFFFFFFu, i, 0);

    while (i < NN) {
        int nexti = 0;
        if (lane == 0) nexti = atomicAdd(&g_ticket, 1);   // prefetch next ticket

        const float4* Pi = (const float4*)(g_Pi + (size_t)i * 256);
        float4 pif = Pi[lane];
        float4 pis = Pi[32 + lane];
        pif.x += bfv.x; pif.y += bfv.y; pif.z += bfv.z; pif.w += bfv.w;
        pis.x += bsv.x; pis.y += bsv.y; pis.z += bsv.z; pis.w += bsv.w;
        int k = g_roff[i];
        int end = g_cursor[i];
        float4 acc = make_float4(0.f, 0.f, 0.f, 0.f);

        for (; k + 4 <= end; k += 4) {
            int2 p0 = g_epack[k], p1 = g_epack[k + 1];
            int2 p2 = g_epack[k + 2], p3 = g_epack[k + 3];
            float4 f0, q0, f1, q1, f2, q2, f3, q3;
            pj_load(p0.x, lane, f0, q0);
            pj_load(p1.x, lane, f1, q1);
            pj_load(p2.x, lane, f2, q2);
            pj_load(p3.x, lane, f3, q3);
            msg_add(acc, pif, pis, f0, q0, __int_as_float(p0.y), wfe, wse);
            msg_add(acc, pif, pis, f1, q1, __int_as_float(p1.y), wfe, wse);
            msg_add(acc, pif, pis, f2, q2, __int_as_float(p2.y), wfe, wse);
            msg_add(acc, pif, pis, f3, q3, __int_as_float(p3.y), wfe, wse);
        }
        for (; k < end; k++) {
            int2 p0 = g_epack[k];
            float4 f0, q0;
            pj_load(p0.x, lane, f0, q0);
            msg_add(acc, pif, pis, f0, q0, __int_as_float(p0.y), wfe, wse);
        }
        *(float4*)(g_aggr + (size_t)i * CC + c) = acc;
        lsum[0] += acc.x; lsum[1] += acc.y; lsum[2] += acc.z; lsum[3] += acc.w;
        lsq[0] += acc.x * acc.x; lsq[1] += acc.y * acc.y; lsq[2] += acc.z * acc.z; lsq[3] += acc.w * acc.w;

        i = __shfl_sync(0xFFFFFFFFu, nexti, 0);
    }

#pragma unroll
    for (int j = 0; j < 4; j++) {
        atomicAdd(&s_stats[c + j], lsum[j]);
        atomicAdd(&s_stats[CC + c + j], lsq[j]);
    }
    __syncthreads();
    if (tid < 64) {
        float4 v = *(float4*)&s_stats[tid * 4];
        float* dstp = g_stats + tid * 4;
        asm volatile("red.global.add.v4.f32 [%0], {%1, %2, %3, %4};"
                     :: "l"(dstp), "f"(v.x), "f"(v.y), "f"(v.z), "f"(v.w)
                     : "memory");
    }
}

// ---------------- out_final = 2*out + batchnorm(aggr) ----------------
__global__ void finalize(const float* __restrict__ gamma, const float* __restrict__ beta,
                         float* __restrict__ out) {
    int i4 = blockIdx.x * blockDim.x + threadIdx.x;
    if (i4 >= NN * 32) return;
    int c = (i4 & 31) * 4;
    float4 a = *(const float4*)(g_aggr + (size_t)i4 * 4);
    float4 o = *(const float4*)(g_out + (size_t)i4 * 4);
    const float inv = 1.0f / NN;
    float4 r;
#pragma unroll
    for (int j = 0; j < 4; j++) {
        float sum = g_stats[c + j];
        float sq = g_stats[CC + c + j];
        float mean = sum * inv;
        float var = sq * inv - mean * mean;
        float scale = rsqrtf(var + 1e-5f) * gamma[c + j];
        float av = (&a.x)[j];
        float ov = (&o.x)[j];
        (&r.x)[j] = 2.0f * ov + (av - mean) * scale + beta[c + j];
    }
    *(float4*)(out + (size_t)i4 * 4) = r;
}

extern "C" void kernel_launch(void* const* d_in, const int* in_sizes, int n_in,
                              void* d_out, int out_size) {
    const float* h    = (const float*)d_in[0];
    const int*   ei   = (const int*)d_in[1];
    const float* ea   = (const float*)d_in[3];
    const float* W0   = (const float*)d_in[4];
    const float* b0   = (const float*)d_in[5];
    const float* Wsh  = (const float*)d_in[6];
    const float* bsh  = (const float*)d_in[7];
    const float* Wf   = (const float*)d_in[8];
    const float* bf   = (const float*)d_in[9];
    const float* Ws   = (const float*)d_in[10];
    const float* bs   = (const float*)d_in[11];
    const float* gamma = (const float*)d_in[12];
    const float* beta  = (const float*)d_in[13];
    float* out = (float*)d_out;

    static cudaStream_t s2 = nullptr, s3 = nullptr;
    static cudaEvent_t evFork = nullptr, evJoin2 = nullptr, evJoin3 = nullptr;
    static bool attrSet = false;
    const int SMEM_NG = 2 * 128 * LDH * (int)sizeof(__half);
    if (!s2) {
        cudaStreamCreateWithFlags(&s2, cudaStreamNonBlocking);
        cudaStreamCreateWithFlags(&s3, cudaStreamNonBlocking);
        cudaEventCreateWithFlags(&evFork, cudaEventDisableTiming);
        cudaEventCreateWithFlags(&evJoin2, cudaEventDisableTiming);
        cudaEventCreateWithFlags(&evJoin3, cudaEventDisableTiming);
    }
    if (!attrSet) {
        cudaFuncSetAttribute(node_gemms, cudaFuncAttributeMaxDynamicSharedMemorySize, SMEM_NG);
        attrSet = true;
    }

    // ---- fork ----
    cudaEventRecord(evFork, 0);
    cudaStreamWaitEvent(s2, evFork, 0);
    cudaStreamWaitEvent(s3, evFork, 0);

    // branch A (s2): CSR build + edge gaussian
    hist<<<(EE + 255) / 256, 256, 0, s2>>>(ei);
    assign_off<<<(NN + 255) / 256, 256, 0, s2>>>();
    edge_gauss_scatter<<<(EE * 4 + 255) / 256, 256, 0, s2>>>(ea, Wsh, bsh, ei);
    cudaEventRecord(evJoin2, s2);

    // branch B (s3): weight pack + fused node GEMMs (tensor core)
    prep_pack<<<(640 * 128 + 255) / 256, 256, 0, s3>>>(W0, Wf, Ws);
    node_gemms<<<(NN + 127) / 128, 256, SMEM_NG, s3>>>(h, b0);
    cudaEventRecord(evJoin3, s3);

    // ---- join ----
    cudaStreamWaitEvent(0, evJoin2, 0);
    cudaStreamWaitEvent(0, evJoin3, 0);

    edge_msg_csr<<<1536, 256>>>(Wf, Ws, bf, bs);
    finalize<<<(NN * 32 + 255) / 256, 256>>>(gamma, beta, out);
}